// round 4
// baseline (speedup 1.0000x reference)
#include <cuda_runtime.h>
#include <cstdint>

#define DIM   768
#define POOL  20
#define TOPK  9
#define NVEC  6                 // float4 chunks per lane: 768 / 4 / 32
#define WARPS 8
#define ROWS_PER_WARP  2
#define ROWS_PER_BLOCK (WARPS * ROWS_PER_WARP)   // 16
#define MAXB  65536

// Allocation-free scratch
__device__ float        g_kn[POOL * DIM];
__device__ float        g_rowsum[POOL];
__device__ unsigned int g_count[POOL];
__device__ uint64_t     g_idx[MAXB];     // 9 x 7-bit packed topk per row

// ---------------------------------------------------------------------------
// prep: 1 block x 640 threads. Warp w normalizes key row w (shuffle-only).
// ---------------------------------------------------------------------------
__global__ void prep_kernel(const float* __restrict__ keys,
                            const int*   __restrict__ layer)
{
    const int w    = threadIdx.x >> 5;
    const int lane = threadIdx.x & 31;

    if (w < POOL) {
        const float* __restrict__ krow =
            keys + ((size_t)(*layer) * POOL + w) * DIM;
        float ss = 0.f;
        #pragma unroll
        for (int i = 0; i < DIM / 32; i++) {
            float v = __ldg(krow + lane + 32 * i);
            ss += v * v;
        }
        #pragma unroll
        for (int off = 16; off; off >>= 1)
            ss += __shfl_xor_sync(0xffffffffu, ss, off);
        const float inv = 1.f / fmaxf(sqrtf(ss), 1e-12f);
        #pragma unroll
        for (int i = 0; i < DIM / 32; i++)
            g_kn[w * DIM + lane + 32 * i] = __ldg(krow + lane + 32 * i) * inv;
    }
    if (threadIdx.x < POOL) {
        g_count[threadIdx.x]  = 0u;
        g_rowsum[threadIdx.x] = 0.f;
    }
}

// ---------------------------------------------------------------------------
// helper: full sim + top-9 for one row held in registers (warp-collective)
// ---------------------------------------------------------------------------
__device__ __forceinline__ uint64_t topk_pack(float* s)
{
    uint64_t packed = 0;
    #pragma unroll
    for (int t = 0; t < TOPK; t++) {
        float best = -3.4e38f; int bj = 0;
        #pragma unroll
        for (int j = 0; j < POOL; j++)
            if (s[j] > best) { best = s[j]; bj = j; }
        packed |= (uint64_t)bj << (7 * t);
        #pragma unroll
        for (int j = 0; j < POOL; j++)
            if (j == bj) s[j] = -3.4e38f;
    }
    return packed;
}

// ---------------------------------------------------------------------------
// Kernel A: compute sims + top-9 -> packed index per row. No gather here.
// ---------------------------------------------------------------------------
__global__ void __launch_bounds__(256)
pool_compute(const float* __restrict__ x, int B)
{
    __shared__ unsigned int s_count[POOL];
    if (threadIdx.x < POOL) s_count[threadIdx.x] = 0u;
    __syncthreads();

    const int warp = threadIdx.x >> 5;
    const int lane = threadIdx.x & 31;
    const int r0   = blockIdx.x * ROWS_PER_BLOCK + warp * ROWS_PER_WARP;
    const int r1   = r0 + 1;

    if (r1 < B) {
        const float4* __restrict__ xr0 = (const float4*)(x + (size_t)r0 * DIM);
        const float4* __restrict__ xr1 = (const float4*)(x + (size_t)r1 * DIM);
        const float4* __restrict__ knv = (const float4*)g_kn;

        float s0[POOL], s1[POOL];
        #pragma unroll
        for (int j = 0; j < POOL; j++) { s0[j] = 0.f; s1[j] = 0.f; }
        float ss0 = 0.f, ss1 = 0.f;

        #pragma unroll
        for (int i = 0; i < NVEC; i++) {
            const float4 xv0 = __ldcs(xr0 + lane + 32 * i);
            const float4 xv1 = __ldcs(xr1 + lane + 32 * i);
            ss0 += xv0.x * xv0.x + xv0.y * xv0.y + xv0.z * xv0.z + xv0.w * xv0.w;
            ss1 += xv1.x * xv1.x + xv1.y * xv1.y + xv1.z * xv1.z + xv1.w * xv1.w;
            #pragma unroll
            for (int j = 0; j < POOL; j++) {
                const float4 kv = __ldg(knv + j * (DIM / 4) + lane + 32 * i);
                s0[j] += xv0.x * kv.x + xv0.y * kv.y + xv0.z * kv.z + xv0.w * kv.w;
                s1[j] += xv1.x * kv.x + xv1.y * kv.y + xv1.z * kv.z + xv1.w * kv.w;
            }
        }

        #pragma unroll
        for (int off = 16; off; off >>= 1) {
            ss0 += __shfl_xor_sync(0xffffffffu, ss0, off);
            ss1 += __shfl_xor_sync(0xffffffffu, ss1, off);
            #pragma unroll
            for (int j = 0; j < POOL; j++) {
                s0[j] += __shfl_xor_sync(0xffffffffu, s0[j], off);
                s1[j] += __shfl_xor_sync(0xffffffffu, s1[j], off);
            }
        }

        const float inv0 = 1.f / fmaxf(sqrtf(ss0), 1e-12f);
        const float inv1 = 1.f / fmaxf(sqrtf(ss1), 1e-12f);
        #pragma unroll
        for (int j = 0; j < POOL; j++) { s0[j] *= inv0; s1[j] *= inv1; }

        if (lane == 0) {
            if (r0 < POOL) {
                float rs = 0.f;
                #pragma unroll
                for (int j = 0; j < POOL; j++) rs += s0[j];
                g_rowsum[r0] = rs;
            }
            if (r1 < POOL) {
                float rs = 0.f;
                #pragma unroll
                for (int j = 0; j < POOL; j++) rs += s1[j];
                g_rowsum[r1] = rs;
            }
        }

        const uint64_t p0 = topk_pack(s0);
        const uint64_t p1 = topk_pack(s1);

        if (lane == 0) {
            g_idx[r0] = p0;
            g_idx[r1] = p1;
            #pragma unroll
            for (int t = 0; t < TOPK; t++) {
                atomicAdd(&s_count[(int)((p0 >> (7 * t)) & 127)], 1u);
                atomicAdd(&s_count[(int)((p1 >> (7 * t)) & 127)], 1u);
            }
        }
    } else if (r0 < B) {
        // tail: single row (unused for B=32768 but kept correct)
        const float4* __restrict__ xr0 = (const float4*)(x + (size_t)r0 * DIM);
        const float4* __restrict__ knv = (const float4*)g_kn;
        float s0[POOL];
        #pragma unroll
        for (int j = 0; j < POOL; j++) s0[j] = 0.f;
        float ss0 = 0.f;
        #pragma unroll
        for (int i = 0; i < NVEC; i++) {
            const float4 xv0 = __ldcs(xr0 + lane + 32 * i);
            ss0 += xv0.x * xv0.x + xv0.y * xv0.y + xv0.z * xv0.z + xv0.w * xv0.w;
            #pragma unroll
            for (int j = 0; j < POOL; j++) {
                const float4 kv = __ldg(knv + j * (DIM / 4) + lane + 32 * i);
                s0[j] += xv0.x * kv.x + xv0.y * kv.y + xv0.z * kv.z + xv0.w * kv.w;
            }
        }
        #pragma unroll
        for (int off = 16; off; off >>= 1) {
            ss0 += __shfl_xor_sync(0xffffffffu, ss0, off);
            #pragma unroll
            for (int j = 0; j < POOL; j++)
                s0[j] += __shfl_xor_sync(0xffffffffu, s0[j], off);
        }
        const float inv0 = 1.f / fmaxf(sqrtf(ss0), 1e-12f);
        #pragma unroll
        for (int j = 0; j < POOL; j++) s0[j] *= inv0;
        if (lane == 0 && r0 < POOL) {
            float rs = 0.f;
            #pragma unroll
            for (int j = 0; j < POOL; j++) rs += s0[j];
            g_rowsum[r0] = rs;
        }
        const uint64_t p0 = topk_pack(s0);
        if (lane == 0) {
            g_idx[r0] = p0;
            #pragma unroll
            for (int t = 0; t < TOPK; t++)
                atomicAdd(&s_count[(int)((p0 >> (7 * t)) & 127)], 1u);
        }
    }

    __syncthreads();
    if (threadIdx.x < POOL)
        atomicAdd(&g_count[threadIdx.x], s_count[threadIdx.x]);
}

// ---------------------------------------------------------------------------
// Kernel B: pure gather/copy. One warp per (row, t): 768 floats, coalesced.
// ---------------------------------------------------------------------------
__global__ void __launch_bounds__(256)
pool_gather(const float* __restrict__ prompts,
            const int*   __restrict__ layer,
            float*       __restrict__ out,
            int B)
{
    const int gwarp = (blockIdx.x * blockDim.x + threadIdx.x) >> 5;
    const int lane  = threadIdx.x & 31;
    if (gwarp >= B * TOPK) return;

    const int row = gwarp / TOPK;
    const int t   = gwarp - row * TOPK;

    const int id = (int)((g_idx[row] >> (7 * t)) & 127);

    const float4* __restrict__ src =
        (const float4*)(prompts + ((size_t)(*layer) * POOL + id) * DIM);
    float4* __restrict__ dst =
        (float4*)out + ((size_t)row * TOPK + t) * (DIM / 4);

    #pragma unroll
    for (int i = 0; i < NVEC; i++)
        __stcs(dst + lane + 32 * i, __ldg(src + lane + 32 * i));
}

// ---------------------------------------------------------------------------
// finalize: dist = 1 - sum_r count[r]*rowsum[r] / (B*TOPK*POOL)
// ---------------------------------------------------------------------------
__global__ void finalize_kernel(float* __restrict__ out,
                                long long total, long long out_size, int B)
{
    double s = 0.0;
    #pragma unroll
    for (int r = 0; r < POOL; r++)
        s += (double)g_count[r] * (double)g_rowsum[r];
    const float dist = (float)(1.0 - s / ((double)B * TOPK * POOL));
    for (long long i = total + threadIdx.x; i < out_size; i += blockDim.x)
        out[i] = dist;
}

extern "C" void kernel_launch(void* const* d_in, const int* in_sizes, int n_in,
                              void* d_out, int out_size)
{
    const float* x       = (const float*)d_in[0];
    const float* keys    = (const float*)d_in[1];
    const float* prompts = (const float*)d_in[2];
    const int*   layer   = (const int*)d_in[3];

    const int B = in_sizes[0] / DIM;
    const long long total = (long long)B * TOPK * DIM;

    prep_kernel<<<1, 640>>>(keys, layer);
    pool_compute<<<(B + ROWS_PER_BLOCK - 1) / ROWS_PER_BLOCK, 256>>>(x, B);
    const int gwarps  = B * TOPK;
    const int gblocks = (gwarps * 32 + 255) / 256;
    pool_gather<<<gblocks, 256>>>(prompts, layer, (float*)d_out, B);
    finalize_kernel<<<1, 32>>>((float*)d_out, total, (long long)out_size, B);
}